// round 5
// baseline (speedup 1.0000x reference)
#include <cuda_runtime.h>
#include <math.h>

#define T_STEPS 512
#define BATCH   256
#define IN_DIM  256
#define HID     1024
#define GH      (BATCH * HID)
#define NCTAS   128

#define SROW    40               // padded smem row (u32)
#define WCH     (32 * SROW)      // Whh chunk: 32 rows x 32 k (permuted)
#define HCH     (64 * SROW)      // h  chunk: 64 rows x 32 k (permuted)
#define NKCH    32               // K chunks of 32

// Persistent device state
__device__ unsigned g_h[2 * GH];     // parity double-buffered tf32 h (k-permuted)
__device__ unsigned g_bar_count;
__device__ unsigned g_bar_phase;

__device__ __forceinline__ unsigned f2tf(float f) {
    unsigned u;
    asm("cvt.rna.tf32.f32 %0, %1;" : "=r"(u) : "f"(f));
    return u;
}

__device__ __forceinline__ void mma8(float c[4], const unsigned a[4], const unsigned b[2]) {
    asm volatile(
        "mma.sync.aligned.m16n8k8.row.col.f32.tf32.tf32.f32 "
        "{%0,%1,%2,%3}, {%4,%5,%6,%7}, {%8,%9}, {%0,%1,%2,%3};\n"
        : "+f"(c[0]), "+f"(c[1]), "+f"(c[2]), "+f"(c[3])
        : "r"(a[0]), "r"(a[1]), "r"(a[2]), "r"(a[3]), "r"(b[0]), "r"(b[1]));
}

__device__ __forceinline__ void cp_cg16(unsigned* smem_dst, const unsigned* gmem_src) {
    unsigned s = (unsigned)__cvta_generic_to_shared(smem_dst);
    asm volatile("cp.async.cg.shared.global [%0], [%1], 16;\n" :: "r"(s), "l"(gmem_src));
}
#define CP_COMMIT() asm volatile("cp.async.commit_group;\n")

__device__ __forceinline__ float tanh_fast(float x) {
    float e = __expf(2.0f * x);
    return 1.0f - __fdividef(2.0f, e + 1.0f);
}

// ---------------------------------------------------------------------------
// Kernel 0: g_h parity-0 = tf32(h0), k-permuted [k0,k4,k1,k5,k2,k6,k3,k7]
// ---------------------------------------------------------------------------
__global__ void init_h_kernel(const float* __restrict__ h0) {
    int i = blockIdx.x * blockDim.x + threadIdx.x;   // over 65536 float4
    int row = i >> 8;
    int c0  = (i & 255) * 4;
    const float4 v = *reinterpret_cast<const float4*>(h0 + (size_t)row * HID + c0);
    int base = (c0 & ~7) + ((c0 & 4) ? 1 : 0);
    unsigned* dst = g_h + (size_t)row * HID + base;  // parity 0 (read by step 0)
    dst[0] = f2tf(v.x); dst[2] = f2tf(v.y); dst[4] = f2tf(v.z); dst[6] = f2tf(v.w);
}

// ---------------------------------------------------------------------------
// Precompute: Xpre = input @ Wih^T + bias -> d_out (register-staged prefetch).
// Verified path from R4 (non-permuted smem, scalar frags).
// ---------------------------------------------------------------------------
__device__ __forceinline__ void fetch_tile(const float* __restrict__ g, int ld,
                                           int row0, int col0, float4* v) {
    int f = threadIdx.x;
    #pragma unroll
    for (int it = 0; it < 4; it++, f += 256) {
        int r = f >> 3, c4 = (f & 7) << 2;
        v[it] = *reinterpret_cast<const float4*>(g + (size_t)(row0 + r) * ld + col0 + c4);
    }
}
__device__ __forceinline__ void store_tile(const float4* v, unsigned* s) {
    int f = threadIdx.x;
    #pragma unroll
    for (int it = 0; it < 4; it++, f += 256) {
        int r = f >> 3, c4 = (f & 7) << 2;
        uint4 w;
        w.x = f2tf(v[it].x); w.y = f2tf(v[it].y); w.z = f2tf(v[it].z); w.w = f2tf(v[it].w);
        *reinterpret_cast<uint4*>(s + r * SROW + c4) = w;
    }
}
__device__ __forceinline__ void mma_block_pre(float c[4][4][4],
                                              const unsigned* As, const unsigned* Bs,
                                              int wm, int wn, int g, int tig) {
    #pragma unroll
    for (int ks = 0; ks < 4; ks++) {
        const int k8 = ks * 8;
        unsigned a[4][4], b[4][2];
        #pragma unroll
        for (int mi = 0; mi < 4; mi++) {
            const unsigned* p = As + (wm * 64 + mi * 16 + g) * SROW + k8 + tig;
            a[mi][0] = p[0]; a[mi][1] = p[8 * SROW]; a[mi][2] = p[4]; a[mi][3] = p[8 * SROW + 4];
        }
        #pragma unroll
        for (int ni = 0; ni < 4; ni++) {
            const unsigned* p = Bs + (wn * 32 + ni * 8 + g) * SROW + k8 + tig;
            b[ni][0] = p[0]; b[ni][1] = p[4];
        }
        #pragma unroll
        for (int mi = 0; mi < 4; mi++)
            #pragma unroll
            for (int ni = 0; ni < 4; ni++)
                mma8(c[mi][ni], a[mi], b[ni]);
    }
}

__global__ void __launch_bounds__(256, 1)
precompute_kernel(const float* __restrict__ input, const float* __restrict__ Wih,
                  const float* __restrict__ bias, float* __restrict__ out) {
    __shared__ unsigned As[128 * SROW];
    __shared__ unsigned Bs[128 * SROW];

    const int m0 = blockIdx.y * 128;
    const int n0 = blockIdx.x * 128;
    const int warp = threadIdx.x >> 5, lane = threadIdx.x & 31;
    const int wm = warp >> 2, wn = warp & 3, g = lane >> 2, tig = lane & 3;

    float c[4][4][4];
    #pragma unroll
    for (int i = 0; i < 4; i++)
        #pragma unroll
        for (int j = 0; j < 4; j++)
            #pragma unroll
            for (int k = 0; k < 4; k++) c[i][j][k] = 0.f;

    float4 pa[4], pb[4];
    fetch_tile(input, IN_DIM, m0, 0, pa);
    fetch_tile(Wih,   IN_DIM, n0, 0, pb);

    for (int kc = 0; kc < IN_DIM; kc += 32) {
        store_tile(pa, As);
        store_tile(pb, Bs);
        __syncthreads();
        if (kc + 32 < IN_DIM) {
            fetch_tile(input, IN_DIM, m0, kc + 32, pa);
            fetch_tile(Wih,   IN_DIM, n0, kc + 32, pb);
        }
        mma_block_pre(c, As, Bs, wm, wn, g, tig);
        __syncthreads();
    }

    #pragma unroll
    for (int mi = 0; mi < 4; mi++) {
        const int row = m0 + wm * 64 + mi * 16 + g;
        #pragma unroll
        for (int ni = 0; ni < 4; ni++) {
            const int col = n0 + wn * 32 + ni * 8 + 2 * tig;
            const float b0 = bias[col], b1 = bias[col + 1];
            float2 v0 = make_float2(c[mi][ni][0] + b0, c[mi][ni][1] + b1);
            float2 v1 = make_float2(c[mi][ni][2] + b0, c[mi][ni][3] + b1);
            *reinterpret_cast<float2*>(out + (size_t)row * HID + col)       = v0;
            *reinterpret_cast<float2*>(out + (size_t)(row + 8) * HID + col) = v1;
        }
    }
}

// ---------------------------------------------------------------------------
// Grid barrier (proven): tight spin, phase-based, graph-replay safe.
// ---------------------------------------------------------------------------
__device__ __forceinline__ void grid_barrier() {
    __threadfence();
    __syncthreads();
    if (threadIdx.x == 0) {
        const unsigned phase = *(volatile unsigned*)&g_bar_phase;
        if (atomicAdd(&g_bar_count, 1u) == NCTAS - 1) {
            atomicExch(&g_bar_count, 0u);
            __threadfence();
            atomicAdd(&g_bar_phase, 1u);
        } else {
            while (*(volatile unsigned*)&g_bar_phase == phase) { }
        }
        __threadfence();
    }
    __syncthreads();
}

// ---------------------------------------------------------------------------
// Recurrence: 128 CTAs = M64 x N32 tiles, FULL K=1024 (no split-K!).
// Whh slice (32x1024) resident in permuted tf32 smem; h streamed via
// cp.async.cg ring from parity-buffered g_h. ONE grid barrier per step.
// ---------------------------------------------------------------------------
__device__ __forceinline__ void issue_h(unsigned* hb, const unsigned* ghsrc, int kb) {
    unsigned* dst = hb + (kb & 3) * HCH;
    const unsigned* src = ghsrc + kb * 32;
    int e = threadIdx.x;
    #pragma unroll
    for (int it = 0; it < 2; it++, e += 256) {
        int r = e >> 3, g4 = (e & 7) * 4;
        cp_cg16(dst + r * SROW + g4, src + (size_t)r * HID + g4);
    }
}

// warp tile m16 x n16; c[ni][4]
__device__ __forceinline__ void mma_chunk(float c[2][4],
                                          const unsigned* As, const unsigned* Bs,
                                          int wm, int wn, int g, int tig) {
    #pragma unroll
    for (int ks = 0; ks < 4; ks++) {
        const int ko = ks * 8 + 2 * tig;   // permuted: (k_tig, k_tig+4) adjacent
        uint2 alo = *reinterpret_cast<const uint2*>(As + (wm * 16 + g) * SROW + ko);
        uint2 ahi = *reinterpret_cast<const uint2*>(As + (wm * 16 + g + 8) * SROW + ko);
        unsigned a[4] = {alo.x, ahi.x, alo.y, ahi.y};
        #pragma unroll
        for (int ni = 0; ni < 2; ni++) {
            uint2 bb = *reinterpret_cast<const uint2*>(Bs + (wn * 16 + ni * 8 + g) * SROW + ko);
            unsigned b2[2] = {bb.x, bb.y};
            mma8(c[ni], a, b2);
        }
    }
}

__global__ void __launch_bounds__(256, 1)
recurrence_kernel(const float* __restrict__ h0, const float* __restrict__ Whh,
                  float* __restrict__ out, int write_tail) {
    extern __shared__ unsigned smem[];
    unsigned* whh  = smem;                 // 32 * WCH (resident, permuted tf32) = 160 KB
    unsigned* hbuf = smem + NKCH * WCH;    // 4 * HCH ring = 40 KB

    const int cta = blockIdx.x;            // 0..127
    const int nt  = cta >> 2;              // 0..31 (32-col hidden block)
    const int mt  = cta & 3;               // 0..3  (64-row batch block)
    const int m0  = mt * 64;
    const int n0  = nt * 32;

    const int warp = threadIdx.x >> 5, lane = threadIdx.x & 31;
    const int wm = warp & 3, wn = warp >> 2, g = lane >> 2, tig = lane & 3;

    // One-time: resident Whh slice [n0..n0+32) x [0..1024) -> permuted tf32
    for (int kb = 0; kb < NKCH; kb++) {
        unsigned* ws = whh + kb * WCH;
        int r = threadIdx.x >> 3, c4 = (threadIdx.x & 7) * 4;
        const float4 v = *reinterpret_cast<const float4*>(
            Whh + (size_t)(n0 + r) * HID + kb * 32 + c4);
        int base = (c4 & ~7) + ((c4 & 4) ? 1 : 0);
        ws[r * SROW + base + 0] = f2tf(v.x);
        ws[r * SROW + base + 2] = f2tf(v.y);
        ws[r * SROW + base + 4] = f2tf(v.z);
        ws[r * SROW + base + 6] = f2tf(v.w);
    }
    __syncthreads();

    // Thread-owned output coords (mma accumulator layout) + fp32 h in registers.
    const int r0 = m0 + wm * 16 + g;
    const int r1 = r0 + 8;
    float hreg[2][4];
    #pragma unroll
    for (int ni = 0; ni < 2; ni++) {
        const int col = n0 + wn * 16 + ni * 8 + 2 * tig;
        const float2 a0 = *reinterpret_cast<const float2*>(h0 + (size_t)r0 * HID + col);
        const float2 a1 = *reinterpret_cast<const float2*>(h0 + (size_t)r1 * HID + col);
        hreg[ni][0] = a0.x; hreg[ni][1] = a0.y;
        hreg[ni][2] = a1.x; hreg[ni][3] = a1.y;
    }

    for (int t = 0; t < T_STEPS; t++) {
        const unsigned* ghsrc = g_h + (size_t)(t & 1) * GH + (size_t)m0 * HID;

        issue_h(hbuf, ghsrc, 0); CP_COMMIT();
        issue_h(hbuf, ghsrc, 1); CP_COMMIT();
        issue_h(hbuf, ghsrc, 2); CP_COMMIT();

        float c[2][4];
        #pragma unroll
        for (int i = 0; i < 2; i++)
            #pragma unroll
            for (int j = 0; j < 4; j++) c[i][j] = 0.f;

        // chunks 0..29: keep 3 in flight
        for (int kb = 0; kb < NKCH - 2; kb++) {
            asm volatile("cp.async.wait_group %0;\n" :: "n"(2));
            __syncthreads();
            if (kb + 3 < NKCH) { issue_h(hbuf, ghsrc, kb + 3); CP_COMMIT(); }
            mma_chunk(c, hbuf + (kb & 3) * HCH, whh + kb * WCH, wm, wn, g, tig);
        }
        // tail chunks 30, 31
        asm volatile("cp.async.wait_group %0;\n" :: "n"(1));
        __syncthreads();
        mma_chunk(c, hbuf + ((NKCH - 2) & 3) * HCH, whh + (NKCH - 2) * WCH, wm, wn, g, tig);
        asm volatile("cp.async.wait_group %0;\n" :: "n"(0));
        __syncthreads();
        mma_chunk(c, hbuf + ((NKCH - 1) & 3) * HCH, whh + (NKCH - 1) * WCH, wm, wn, g, tig);

        // ---- Epilogue (thread-local): Xpre + tanh + EMA -> out, g_h[parity^1] ----
        {
            float* dst = out + (size_t)t * GH;
            unsigned* ghw = g_h + (size_t)((t + 1) & 1) * GH;
            #pragma unroll
            for (int ni = 0; ni < 2; ni++) {
                const int col = n0 + wn * 16 + ni * 8 + 2 * tig;
                const float2 x0 = *reinterpret_cast<const float2*>(dst + (size_t)r0 * HID + col);
                const float2 x1 = *reinterpret_cast<const float2*>(dst + (size_t)r1 * HID + col);
                float v0 = fmaf(0.9f, hreg[ni][0], 0.1f * tanh_fast(c[ni][0] + x0.x));
                float v1 = fmaf(0.9f, hreg[ni][1], 0.1f * tanh_fast(c[ni][1] + x0.y));
                float v2 = fmaf(0.9f, hreg[ni][2], 0.1f * tanh_fast(c[ni][2] + x1.x));
                float v3 = fmaf(0.9f, hreg[ni][3], 0.1f * tanh_fast(c[ni][3] + x1.y));
                hreg[ni][0] = v0; hreg[ni][1] = v1; hreg[ni][2] = v2; hreg[ni][3] = v3;
                *reinterpret_cast<float2*>(dst + (size_t)r0 * HID + col) = make_float2(v0, v1);
                *reinterpret_cast<float2*>(dst + (size_t)r1 * HID + col) = make_float2(v2, v3);

                // permuted tf32 store: pair (col, col+1) -> positions b, b+2
                const int b = (col & ~7) + 2 * (col & 3) + ((col & 4) ? 1 : 0);
                unsigned* gp0 = ghw + (size_t)r0 * HID + b;
                unsigned* gp1 = ghw + (size_t)r1 * HID + b;
                gp0[0] = f2tf(v0); gp0[2] = f2tf(v1);
                gp1[0] = f2tf(v2); gp1[2] = f2tf(v3);

                if (write_tail && t == T_STEPS - 1) {
                    float* tl = out + (size_t)T_STEPS * GH;
                    *reinterpret_cast<float2*>(tl + (size_t)r0 * HID + col) = make_float2(v0, v1);
                    *reinterpret_cast<float2*>(tl + (size_t)r1 * HID + col) = make_float2(v2, v3);
                }
            }
        }

        grid_barrier();   // single per-step convergence
    }
}

extern "C" void kernel_launch(void* const* d_in, const int* in_sizes, int n_in,
                              void* d_out, int out_size) {
    const float* input = (const float*)d_in[0];  // [512, 256, 256]
    const float* h0    = (const float*)d_in[1];  // [1, 256, 1024]
    const float* Wih   = (const float*)d_in[2];  // [1024, 256]
    const float* Whh   = (const float*)d_in[3];  // [1024, 1024]
    const float* bias  = (const float*)d_in[4];  // [1024]
    float* out = (float*)d_out;

    const int write_tail = (out_size >= T_STEPS * GH + GH) ? 1 : 0;

    static const int SMEM_BYTES = (NKCH * WCH + 4 * HCH) * 4;  // 204800
    cudaFuncSetAttribute(recurrence_kernel,
                         cudaFuncAttributeMaxDynamicSharedMemorySize, SMEM_BYTES);

    init_h_kernel<<<GH / 4 / 256, 256>>>(h0);
    precompute_kernel<<<dim3(HID / 128, (T_STEPS * BATCH) / 128), 256>>>(input, Wih, bias, out);
    recurrence_kernel<<<NCTAS, 256, SMEM_BYTES>>>(h0, Whh, out, write_tail);
}

// round 10
// speedup vs baseline: 1.3046x; 1.3046x over previous
#include <cuda_runtime.h>
#include <math.h>

#define T_STEPS 512
#define BATCH   256
#define IN_DIM  256
#define HID     1024
#define GH      (BATCH * HID)
#define NCTAS   128

#define SROW     40              // padded smem row (u32): conflict-free, LDS.64-friendly
#define HCHUNK   (64 * SROW)     // h chunk: 64 rows x 32 k (permuted)
#define WCHUNK   (128 * SROW)    // Whh chunk: 128 rows x 32 k (permuted)
#define TILEPART (64 * 128)      // one CTA's partial tile

// Persistent device state
__device__ float    g_partial[NCTAS * TILEPART];  // 4 MB split-K partials
__device__ unsigned g_h[GH];                      // tf32 h_t (k-permuted)
// Group barriers: one 128B line each: [0]=count, [16]=phase. Zero-init;
// count self-resets, phase is monotonic -> graph-replay safe.
__device__ unsigned g_tbar[32 * 32];              // per-tile (4-CTA) barriers
__device__ unsigned g_mbar[4 * 32];               // per-mt  (32-CTA) barriers

__device__ __forceinline__ unsigned f2tf(float f) {
    unsigned u;
    asm("cvt.rna.tf32.f32 %0, %1;" : "=r"(u) : "f"(f));
    return u;
}

__device__ __forceinline__ void mma8(float c[4], const unsigned a[4], const unsigned b[2]) {
    asm volatile(
        "mma.sync.aligned.m16n8k8.row.col.f32.tf32.tf32.f32 "
        "{%0,%1,%2,%3}, {%4,%5,%6,%7}, {%8,%9}, {%0,%1,%2,%3};\n"
        : "+f"(c[0]), "+f"(c[1]), "+f"(c[2]), "+f"(c[3])
        : "r"(a[0]), "r"(a[1]), "r"(a[2]), "r"(a[3]), "r"(b[0]), "r"(b[1]));
}

__device__ __forceinline__ void cp_cg16(unsigned* smem_dst, const unsigned* gmem_src) {
    unsigned s = (unsigned)__cvta_generic_to_shared(smem_dst);
    asm volatile("cp.async.cg.shared.global [%0], [%1], 16;\n" :: "r"(s), "l"(gmem_src));
}
#define CP_COMMIT() asm volatile("cp.async.commit_group;\n")

__device__ __forceinline__ float tanh_fast(float x) {
    float e = __expf(2.0f * x);
    return 1.0f - __fdividef(2.0f, e + 1.0f);
}

// ---------------------------------------------------------------------------
// Kernel 0: g_h = tf32(h0), k-permuted [k0,k4,k1,k5,k2,k6,k3,k7].
// ---------------------------------------------------------------------------
__global__ void init_h_kernel(const float* __restrict__ h0) {
    int i = blockIdx.x * blockDim.x + threadIdx.x;   // over 65536 float4
    int row = i >> 8;
    int c0  = (i & 255) * 4;
    const float4 v = *reinterpret_cast<const float4*>(h0 + (size_t)row * HID + c0);
    int base = (c0 & ~7) + ((c0 & 4) ? 1 : 0);
    unsigned* dst = g_h + (size_t)row * HID + base;
    dst[0] = f2tf(v.x); dst[2] = f2tf(v.y); dst[4] = f2tf(v.z); dst[6] = f2tf(v.w);
}

// ---------------------------------------------------------------------------
// Precompute (proven R4 path): Xpre = input @ Wih^T + bias -> d_out
// ---------------------------------------------------------------------------
__device__ __forceinline__ void fetch_tile(const float* __restrict__ g, int ld,
                                           int row0, int col0, float4* v) {
    int f = threadIdx.x;
    #pragma unroll
    for (int it = 0; it < 4; it++, f += 256) {
        int r = f >> 3, c4 = (f & 7) << 2;
        v[it] = *reinterpret_cast<const float4*>(g + (size_t)(row0 + r) * ld + col0 + c4);
    }
}
__device__ __forceinline__ void store_tile(const float4* v, unsigned* s) {
    int f = threadIdx.x;
    #pragma unroll
    for (int it = 0; it < 4; it++, f += 256) {
        int r = f >> 3, c4 = (f & 7) << 2;
        uint4 w;
        w.x = f2tf(v[it].x); w.y = f2tf(v[it].y); w.z = f2tf(v[it].z); w.w = f2tf(v[it].w);
        *reinterpret_cast<uint4*>(s + r * SROW + c4) = w;
    }
}
__device__ __forceinline__ void mma_block_pre(float c[4][4][4],
                                              const unsigned* As, const unsigned* Bs,
                                              int wm, int wn, int g, int tig) {
    #pragma unroll
    for (int ks = 0; ks < 4; ks++) {
        const int k8 = ks * 8;
        unsigned a[4][4], b[4][2];
        #pragma unroll
        for (int mi = 0; mi < 4; mi++) {
            const unsigned* p = As + (wm * 64 + mi * 16 + g) * SROW + k8 + tig;
            a[mi][0] = p[0]; a[mi][1] = p[8 * SROW]; a[mi][2] = p[4]; a[mi][3] = p[8 * SROW + 4];
        }
        #pragma unroll
        for (int ni = 0; ni < 4; ni++) {
            const unsigned* p = Bs + (wn * 32 + ni * 8 + g) * SROW + k8 + tig;
            b[ni][0] = p[0]; b[ni][1] = p[4];
        }
        #pragma unroll
        for (int mi = 0; mi < 4; mi++)
            #pragma unroll
            for (int ni = 0; ni < 4; ni++)
                mma8(c[mi][ni], a[mi], b[ni]);
    }
}

__global__ void __launch_bounds__(256, 1)
precompute_kernel(const float* __restrict__ input, const float* __restrict__ Wih,
                  const float* __restrict__ bias, float* __restrict__ out) {
    __shared__ unsigned As[128 * SROW];
    __shared__ unsigned Bs[128 * SROW];

    const int m0 = blockIdx.y * 128;
    const int n0 = blockIdx.x * 128;
    const int warp = threadIdx.x >> 5, lane = threadIdx.x & 31;
    const int wm = warp >> 2, wn = warp & 3, g = lane >> 2, tig = lane & 3;

    float c[4][4][4];
    #pragma unroll
    for (int i = 0; i < 4; i++)
        #pragma unroll
        for (int j = 0; j < 4; j++)
            #pragma unroll
            for (int k = 0; k < 4; k++) c[i][j][k] = 0.f;

    float4 pa[4], pb[4];
    fetch_tile(input, IN_DIM, m0, 0, pa);
    fetch_tile(Wih,   IN_DIM, n0, 0, pb);

    for (int kc = 0; kc < IN_DIM; kc += 32) {
        store_tile(pa, As);
        store_tile(pb, Bs);
        __syncthreads();
        if (kc + 32 < IN_DIM) {
            fetch_tile(input, IN_DIM, m0, kc + 32, pa);
            fetch_tile(Wih,   IN_DIM, n0, kc + 32, pb);
        }
        mma_block_pre(c, As, Bs, wm, wn, g, tig);
        __syncthreads();
    }

    #pragma unroll
    for (int mi = 0; mi < 4; mi++) {
        const int row = m0 + wm * 64 + mi * 16 + g;
        #pragma unroll
        for (int ni = 0; ni < 4; ni++) {
            const int col = n0 + wn * 32 + ni * 8 + 2 * tig;
            const float b0 = bias[col], b1 = bias[col + 1];
            float2 v0 = make_float2(c[mi][ni][0] + b0, c[mi][ni][1] + b1);
            float2 v1 = make_float2(c[mi][ni][2] + b0, c[mi][ni][3] + b1);
            *reinterpret_cast<float2*>(out + (size_t)row * HID + col)       = v0;
            *reinterpret_cast<float2*>(out + (size_t)(row + 8) * HID + col) = v1;
        }
    }
}

// ---------------------------------------------------------------------------
// Group barrier: PROVEN atomic pattern (atomicAdd count + phase bump + volatile
// spin), scoped to n CTAs sharing one barrier line. Graph-replay safe.
// ---------------------------------------------------------------------------
__device__ __forceinline__ void group_barrier(unsigned* bar, unsigned n) {
    unsigned* cnt   = bar;
    unsigned* phase = bar + 16;
    __threadfence();
    __syncthreads();
    if (threadIdx.x == 0) {
        const unsigned ph = *(volatile unsigned*)phase;
        if (atomicAdd(cnt, 1u) == n - 1) {
            atomicExch(cnt, 0u);
            __threadfence();
            atomicAdd(phase, 1u);
        } else {
            while (*(volatile unsigned*)phase == ph) { }
        }
        __threadfence();
    }
    __syncthreads();
}

// ---------------------------------------------------------------------------
// Recurrence: 128 CTAs = 32 tiles (M64 x N128) x split-K-4.
// Sync is SCOPED: tile-group (4 CTAs) barrier before reduce, mt-group
// (32 CTAs) barrier before next step. No full-grid convergence.
// ---------------------------------------------------------------------------
__device__ __forceinline__ void issue_h(unsigned* hb, const unsigned* ghsrc, int kb) {
    unsigned* dst = hb + (kb & 3) * HCHUNK;
    const unsigned* src = ghsrc + kb * 32;
    int e = threadIdx.x;
    #pragma unroll
    for (int it = 0; it < 2; it++, e += 256) {
        int r = e >> 3, g4 = (e & 7) * 4;
        cp_cg16(dst + r * SROW + g4, src + (size_t)r * HID + g4);
    }
}

__device__ __forceinline__ void mma_chunk(float c[2][4][4],
                                          const unsigned* As, const unsigned* Bs,
                                          int wm, int wn, int g, int tig) {
    #pragma unroll
    for (int ks = 0; ks < 4; ks++) {
        const int ko = ks * 8 + 2 * tig;   // permuted: (k_tig, k_tig+4) adjacent
        uint2 alo[2], ahi[2], bb[4];
        #pragma unroll
        for (int mi = 0; mi < 2; mi++) {
            const unsigned* p = As + (wm * 32 + mi * 16 + g) * SROW + ko;
            alo[mi] = *reinterpret_cast<const uint2*>(p);
            ahi[mi] = *reinterpret_cast<const uint2*>(p + 8 * SROW);
        }
        #pragma unroll
        for (int ni = 0; ni < 4; ni++)
            bb[ni] = *reinterpret_cast<const uint2*>(Bs + (wn * 32 + ni * 8 + g) * SROW + ko);
        #pragma unroll
        for (int mi = 0; mi < 2; mi++) {
            unsigned a[4] = {alo[mi].x, ahi[mi].x, alo[mi].y, ahi[mi].y};
            #pragma unroll
            for (int ni = 0; ni < 4; ni++) {
                unsigned b2[2] = {bb[ni].x, bb[ni].y};
                mma8(c[mi][ni], a, b2);
            }
        }
    }
}

__global__ void __launch_bounds__(256, 1)
recurrence_kernel(const float* __restrict__ h0, const float* __restrict__ Whh,
                  float* __restrict__ out, int write_tail) {
    extern __shared__ unsigned smem[];
    unsigned* whh  = smem;                // 8 * WCHUNK (resident, permuted tf32)
    unsigned* hbuf = smem + 8 * WCHUNK;   // 4 * HCHUNK ring

    const int cta  = blockIdx.x;          // 0..127
    const int tile = cta >> 2;            // 0..31
    const int sub  = cta & 3;             // K-split
    const int mt   = tile >> 3;           // 0..3   (64-row batch block)
    const int nt   = tile & 7;            // 0..7   (128-col hidden block)
    const int m0   = mt * 64;
    const int n0   = nt * 128;
    const int kc0  = sub * 256;

    const int warp = threadIdx.x >> 5, lane = threadIdx.x & 31;
    const int wm = warp >> 2, wn = warp & 3, g = lane >> 2, tig = lane & 3;

    unsigned* tbar = &g_tbar[tile * 32];  // 4-CTA barrier (this tile's subs)
    unsigned* mbar = &g_mbar[mt * 32];    // 32-CTA barrier (this mt group)

    // One-time: resident Whh slice [n0..n0+128) x [kc0..kc0+256) -> permuted tf32
    #pragma unroll
    for (int kb = 0; kb < 8; kb++) {
        unsigned* ws = whh + kb * WCHUNK;
        int e = threadIdx.x;
        #pragma unroll
        for (int it = 0; it < 4; it++, e += 256) {
            int r = e >> 3, c4 = (e & 7) * 4;
            const float4 v = *reinterpret_cast<const float4*>(
                Whh + (size_t)(n0 + r) * HID + kc0 + kb * 32 + c4);
            int base = (c4 & ~7) + ((c4 & 4) ? 1 : 0);
            ws[r * SROW + base + 0] = f2tf(v.x);
            ws[r * SROW + base + 2] = f2tf(v.y);
            ws[r * SROW + base + 4] = f2tf(v.z);
            ws[r * SROW + base + 6] = f2tf(v.w);
        }
    }

    // Phase-B partition is CTA-stationary: keep h (fp32) in registers.
    int rowv[2], colv[2];
    float4 hreg[2];
    {
        int e = threadIdx.x;
        #pragma unroll
        for (int it = 0; it < 2; it++, e += 256) {
            int ml = e >> 5, c4 = (e & 31) * 4;
            rowv[it] = m0 + sub * 16 + ml;
            colv[it] = n0 + c4;
            hreg[it] = *reinterpret_cast<const float4*>(h0 + (size_t)rowv[it] * HID + colv[it]);
        }
    }

    const unsigned* ghsrc = g_h + (size_t)m0 * HID + kc0;
    float* myPart = g_partial + (size_t)cta * TILEPART;

    for (int t = 0; t < T_STEPS; t++) {
        // ---- Phase A: pipelined split-K GEMM over kc0..kc0+256 ----
        issue_h(hbuf, ghsrc, 0); CP_COMMIT();
        issue_h(hbuf, ghsrc, 1); CP_COMMIT();
        issue_h(hbuf, ghsrc, 2); CP_COMMIT();

        float c[2][4][4];
        #pragma unroll
        for (int i = 0; i < 2; i++)
            #pragma unroll
            for (int j = 0; j < 4; j++)
                #pragma unroll
                for (int k = 0; k < 4; k++) c[i][j][k] = 0.f;

#define STEP_KB(KB, WN)                                                      \
        asm volatile("cp.async.wait_group %0;\n" :: "n"(WN));                \
        __syncthreads();                                                     \
        if ((KB) + 3 < 8) { issue_h(hbuf, ghsrc, (KB) + 3); CP_COMMIT(); }   \
        mma_chunk(c, hbuf + ((KB) & 3) * HCHUNK, whh + (KB) * WCHUNK, wm, wn, g, tig);

        STEP_KB(0, 2) STEP_KB(1, 2) STEP_KB(2, 2) STEP_KB(3, 2)
        STEP_KB(4, 2) STEP_KB(5, 2) STEP_KB(6, 1) STEP_KB(7, 0)
#undef STEP_KB

        // store partial tile
        #pragma unroll
        for (int mi = 0; mi < 2; mi++) {
            const int lr = wm * 32 + mi * 16 + g;
            #pragma unroll
            for (int ni = 0; ni < 4; ni++) {
                const int lc = wn * 32 + ni * 8 + 2 * tig;
                *reinterpret_cast<float2*>(myPart + lr * 128 + lc) =
                    make_float2(c[mi][ni][0], c[mi][ni][1]);
                *reinterpret_cast<float2*>(myPart + (lr + 8) * 128 + lc) =
                    make_float2(c[mi][ni][2], c[mi][ni][3]);
            }
        }

        // ---- Xpre prefetch: own exclusive out[t] region; overlaps barrier ----
        float* dst = out + (size_t)t * GH;
        float4 xreg[2];
        #pragma unroll
        for (int it = 0; it < 2; it++)
            xreg[it] = __ldcg(reinterpret_cast<const float4*>(
                dst + (size_t)rowv[it] * HID + colv[it]));

        group_barrier(tbar, 4);   // tile group: partials ready

        // ---- Phase B: reduce 4 partials + Xpre -> tanh -> EMA -> out, g_h ----
        {
            const float* pb = g_partial + (size_t)(tile * 4) * TILEPART;
            int e = threadIdx.x;
            #pragma unroll
            for (int it = 0; it < 2; it++, e += 256) {
                const int ml = e >> 5, c4 = (e & 31) * 4;
                const int lr = sub * 16 + ml;
                const int row = rowv[it], col = colv[it];

                float4 acc = xreg[it];
                #pragma unroll
                for (int s = 0; s < 4; s++) {
                    const float4 p = __ldcg(reinterpret_cast<const float4*>(
                        pb + (size_t)s * TILEPART + lr * 128 + c4));
                    acc.x += p.x; acc.y += p.y; acc.z += p.z; acc.w += p.w;
                }
                float4 r;
                r.x = fmaf(0.9f, hreg[it].x, 0.1f * tanh_fast(acc.x));
                r.y = fmaf(0.9f, hreg[it].y, 0.1f * tanh_fast(acc.y));
                r.z = fmaf(0.9f, hreg[it].z, 0.1f * tanh_fast(acc.z));
                r.w = fmaf(0.9f, hreg[it].w, 0.1f * tanh_fast(acc.w));
                hreg[it] = r;
                *reinterpret_cast<float4*>(dst + (size_t)row * HID + col) = r;

                const int base = (col & ~7) + ((col & 4) ? 1 : 0);
                unsigned* gp = g_h + (size_t)row * HID + base;
                gp[0] = f2tf(r.x); gp[2] = f2tf(r.y); gp[4] = f2tf(r.z); gp[6] = f2tf(r.w);

                if (write_tail && t == T_STEPS - 1) {
                    *reinterpret_cast<float4*>(
                        out + (size_t)T_STEPS * GH + (size_t)row * HID + col) = r;
                }
            }
        }

        group_barrier(mbar, 32);  // mt group: h rows ready + partials reusable
    }
}

extern "C" void kernel_launch(void* const* d_in, const int* in_sizes, int n_in,
                              void* d_out, int out_size) {
    const float* input = (const float*)d_in[0];  // [512, 256, 256]
    const float* h0    = (const float*)d_in[1];  // [1, 256, 1024]
    const float* Wih   = (const float*)d_in[2];  // [1024, 256]
    const float* Whh   = (const float*)d_in[3];  // [1024, 1024]
    const float* bias  = (const float*)d_in[4];  // [1024]
    float* out = (float*)d_out;

    const int write_tail = (out_size >= T_STEPS * GH + GH) ? 1 : 0;

    static const int SMEM_BYTES = (8 * WCHUNK + 4 * HCHUNK) * 4;  // 204800
    cudaFuncSetAttribute(recurrence_kernel,
                         cudaFuncAttributeMaxDynamicSharedMemorySize, SMEM_BYTES);

    init_h_kernel<<<GH / 4 / 256, 256>>>(h0);
    precompute_kernel<<<dim3(HID / 128, (T_STEPS * BATCH) / 128), 256>>>(input, Wih, bias, out);
    recurrence_kernel<<<NCTAS, 256, SMEM_BYTES>>>(h0, Whh, out, write_tail);
}